// round 14
// baseline (speedup 1.0000x reference)
#include <cuda_runtime.h>

#define DEPTH   8
#define NCLASS  10
#define NT      64
#define NREG    32    // float2 elements per thread; NT*NREG = 2048 = DIM/2

typedef unsigned long long u64;

// Swizzle v2: bit0 NOT swizzled -> gather/store-A bases are always even,
// enabling compile-time 128-bit pairing. Conflict-freedom re-verified for
// all four access patterns (see derivation in commit message).
__device__ __host__ constexpr int Sz2(int e) {
    return e ^ ((e >> 5) & 14) ^ (((e >> 10) & 1) << 3);
}
// CNOT-layer composite map in element space: old_e = Emap(new_e).
__device__ __host__ constexpr int Emap(int e) {
    return e ^ (e >> 1) ^ ((e >> 2) & 0x2AA);
}
__device__ __host__ constexpr int CBr(int r)  { return (r << 5) ^ (r & 14); } // Sz2(r<<5)
__device__ __host__ constexpr int CGr(int r)  { return Emap(r); }  // == Sz2(Emap(r)), r<32
__device__ __host__ constexpr bool SWP(int r) { return ((r ^ (r >> 1)) & 1) != 0; }

#define PACK2(d,x,y)   asm("mov.b64 %0,{%1,%2};" : "=l"(d) : "f"(x),"f"(y))
#define UNPACK2(x,y,d) asm("mov.b64 {%0,%1},%2;" : "=f"(x),"=f"(y) : "l"(d))
#define MUL2(d,a,b)    asm("mul.rn.f32x2 %0,%1,%2;" : "=l"(d) : "l"(a),"l"(b))
#define FMA2(d,a,b,c)  asm("fma.rn.f32x2 %0,%1,%2,%3;" : "=l"(d) : "l"(a),"l"(b),"l"(c))

// Scaled-shear RY butterfly on 32 u64 regs along register-bit mask m.
// Cos factors hoisted out (global product applied to final probabilities).
__device__ __forceinline__ void shear32(u64* P, int m, u64 T2, u64 NT2) {
#pragma unroll
    for (int k = 0; k < NREG; k++)
        if (!(k & m)) {
            u64 n0, n1;
            FMA2(n0, NT2, P[k | m], P[k]);     // b0 = a0 - p*a1
            FMA2(n1, T2,  P[k],     P[k | m]); // b1 = a1 + p*a0
            P[k]     = n0;
            P[k | m] = n1;
        }
}

__global__ __launch_bounds__(NT, 8) void vqc_kernel(const float* __restrict__ X,
                                                    const float* __restrict__ W,
                                                    float* __restrict__ out) {
    __shared__ u64 smB[2048];                         // SINGLE statevector buffer
    __shared__ u64 TT2[DEPTH * 12], NT2s[DEPTH * 12]; // packed tan / -tan
    __shared__ float t0s[DEPTH];                      // scalar tan, qubit 0
    __shared__ float t11s[DEPTH];                     // scalar tan, qubit 11
    __shared__ float cosv[DEPTH * 12];                // per-gate cos (parallel)
    __shared__ float enc0[12], enc1[12];
    __shared__ float red[2][NCLASS];

    const int t = threadIdx.x;

    // ---- coefficient tables (parallel across threads) ----
    for (int i = t; i < DEPTH * 12; i += NT) {
        float s_, c_;
        sincosf(0.5f * W[i], &s_, &c_);
        float tp = s_ / c_;                   // tan(phi/2)
        float nt = -tp;
        u64 a, b;
        PACK2(a, tp, tp);  PACK2(b, nt, nt);
        TT2[i] = a;  NT2s[i] = b;
        cosv[i] = c_;
        const int q = i % 12, k = i / 12;
        if (q == 0)  t0s[k]  = tp;
        if (q == 11) t11s[k] = tp;
    }
    if (t < 12) {
        float s_, c_;
        sincosf(0.5f * X[blockIdx.x * 12 + t], &s_, &c_);
        const float rr = 0.7071067811865476f;
        enc0[t] = (c_ - s_) * rr;
        enc1[t] = (c_ + s_) * rr;
    }
    __syncthreads();

    // ---- per-thread address bases (Sz2; bA and bG are even for all t) ----
    // Tiling A: e = (t<<5)|r   (regs = e4..0 -> qubits 6..10)
    // Tiling B: e = (t0<<10)|(r<<5)|((t>>1)&31)  (regs = e9..5 -> qubits 1..5)
    const int bA = (t << 5) ^ (t & 14) ^ (((t >> 5) & 1) << 3);
    const int bB = (((t & 1) << 10)) ^ ((t >> 1) & 31) ^ ((t & 1) << 3);
    int em = t << 5;
    em = em ^ (em >> 1) ^ ((em >> 2) & 0x2AA);
    const int bG = em ^ ((em >> 5) & 14) ^ (((em >> 10) & 1) << 3);  // even
    const int blkG = bG >> 1;
    const int blkA = bA >> 1;

    // ---- init: product state (H + encoding RY) in tiling B registers ----
    // thread bits: q0<-t0, q6<-t5, q7<-t4, q8<-t3, q9<-t2, q10<-t1
    float base = (t & 1)        ? enc1[0]  : enc0[0];
    base *= ((t >> 5) & 1)      ? enc1[6]  : enc0[6];
    base *= ((t >> 4) & 1)      ? enc1[7]  : enc0[7];
    base *= ((t >> 3) & 1)      ? enc1[8]  : enc0[8];
    base *= ((t >> 2) & 1)      ? enc1[9]  : enc0[9];
    base *= ((t >> 1) & 1)      ? enc1[10] : enc0[10];
    const float bx = base * enc0[11], by = base * enc1[11];

    u64 P[NREG];
#pragma unroll
    for (int r = 0; r < NREG; r++) {
        // reg bits: q1<-r4, q2<-r3, q3<-r2, q4<-r1, q5<-r0
        float rf = (r & 16) ? enc1[1] : enc0[1];
        rf *= (r & 8) ? enc1[2] : enc0[2];
        rf *= (r & 4) ? enc1[3] : enc0[3];
        rf *= (r & 2) ? enc1[4] : enc0[4];
        rf *= (r & 1) ? enc1[5] : enc0[5];
        float x = rf * bx, y = rf * by;
        PACK2(P[r], x, y);
    }

#pragma unroll 1
    for (int k = 0; k < DEPTH; k++) {
        const int kc = k * 12;

        // ---- trip 1: store B (u64) -> gather (u128) + q11 shear ----
#pragma unroll
        for (int r = 0; r < NREG; r++)
            smB[bB ^ CBr(r)] = P[r];
        __syncthreads();                       // store-B visible before gather

        const float t11 = t11s[k];
#pragma unroll
        for (int r = 0; r < NREG; r += 2) {
            // pair (r, r+1) reads one aligned 16-byte block; assignment and
            // component swaps are compile-time (bG even, parity(CGr(r)) = r1).
            const int blk = blkG ^ (CGr(r) >> 1);
            ulonglong2 L = ((const ulonglong2*)smB)[blk];
            const bool hiFirst = ((r >> 1) & 1) != 0;   // parity of CGr(r)
            u64 e0 = hiFirst ? L.y : L.x;               // element for P[r]
            u64 e1 = hiFirst ? L.x : L.y;               // element for P[r+1]
            {
                float x, y;
                UNPACK2(x, y, e0);
                float xx = SWP(r)     ? y : x;
                float yy = SWP(r)     ? x : y;
                float u = fmaf(-t11, yy, xx);
                float v = fmaf( t11, xx, yy);
                PACK2(P[r], u, v);
            }
            {
                float x, y;
                UNPACK2(x, y, e1);
                float xx = SWP(r + 1) ? y : x;
                float yy = SWP(r + 1) ? x : y;
                float u = fmaf(-t11, yy, xx);
                float v = fmaf( t11, xx, yy);
                PACK2(P[r + 1], u, v);
            }
        }
        __syncthreads();                       // gather reads done before store-A
        shear32(P, 16, TT2[kc + 6],  NT2s[kc + 6]);   // q6  <-> r4
        shear32(P, 8,  TT2[kc + 7],  NT2s[kc + 7]);   // q7
        shear32(P, 4,  TT2[kc + 8],  NT2s[kc + 8]);   // q8
        shear32(P, 2,  TT2[kc + 9],  NT2s[kc + 9]);   // q9
        shear32(P, 1,  TT2[kc + 10], NT2s[kc + 10]);  // q10

        // ---- trip 2: store A (u128) -> load B (u64) -> q1..q5 + shfl q0 ----
#pragma unroll
        for (int r = 0; r < NREG; r += 2) {
            ulonglong2 V;
            V.x = P[r];                        // addr bA^r (even) = low u64
            V.y = P[r + 1];
            ((ulonglong2*)smB)[blkA ^ (r >> 1)] = V;
        }
        __syncthreads();                       // store-A visible before load-B
#pragma unroll
        for (int r = 0; r < NREG; r++)
            P[r] = smB[bB ^ CBr(r)];

        shear32(P, 16, TT2[kc + 1], NT2s[kc + 1]);    // q1 <-> r4
        shear32(P, 8,  TT2[kc + 2], NT2s[kc + 2]);
        shear32(P, 4,  TT2[kc + 3], NT2s[kc + 3]);
        shear32(P, 2,  TT2[kc + 4], NT2s[kc + 4]);
        shear32(P, 1,  TT2[kc + 5], NT2s[kc + 5]);

        // qubit 0 on lane bit t0: shear via shfl (1 FMA2 per reg)
        {
            const float t0c = t0s[k];
            const float te = (t & 1) ? t0c : -t0c;
            u64 TE2;
            PACK2(TE2, te, te);
#pragma unroll
            for (int r = 0; r < NREG; r++) {
                u64 part = __shfl_xor_sync(0xffffffffu, P[r], 1);
                FMA2(P[r], TE2, part, P[r]);   // b = a ± p*partner
            }
        }
    }

    // ---- measurement from registers (tiling B) ----
    float T = 0.0f, A1 = 0.0f, A2 = 0.0f, A3 = 0.0f, A4 = 0.0f, A5 = 0.0f;
#pragma unroll
    for (int r = 0; r < NREG; r++) {
        float x, y;
        UNPACK2(x, y, P[r]);
        float p2 = fmaf(y, y, x * x);
        T += p2;
        if (!(r & 16)) A1 += p2;
        if (!(r & 8))  A2 += p2;
        if (!(r & 4))  A3 += p2;
        if (!(r & 2))  A4 += p2;
        if (!(r & 1))  A5 += p2;
    }
    // global cos-product correction (values computed in parallel earlier)
    float CT = 1.0f;
#pragma unroll
    for (int i = 0; i < DEPTH * 12; i++)
        CT *= cosv[i];
    const float CT2 = CT * CT;
    T *= CT2;  A1 *= CT2;  A2 *= CT2;  A3 *= CT2;  A4 *= CT2;  A5 *= CT2;

    float loc[NCLASS];
    loc[0] = (t & 1)        ? -T : T;
    loc[1] = 2.0f * A1 - T;
    loc[2] = 2.0f * A2 - T;
    loc[3] = 2.0f * A3 - T;
    loc[4] = 2.0f * A4 - T;
    loc[5] = 2.0f * A5 - T;
    loc[6] = ((t >> 5) & 1) ? -T : T;
    loc[7] = ((t >> 4) & 1) ? -T : T;
    loc[8] = ((t >> 3) & 1) ? -T : T;
    loc[9] = ((t >> 2) & 1) ? -T : T;

#pragma unroll
    for (int p = 0; p < NCLASS; p++) {
        float v = loc[p];
#pragma unroll
        for (int o = 16; o > 0; o >>= 1)
            v += __shfl_xor_sync(0xffffffffu, v, o);
        if ((t & 31) == 0) red[t >> 5][p] = v;
    }
    __syncthreads();
    if (t < NCLASS)
        out[blockIdx.x * NCLASS + t] = red[0][t] + red[1][t];
}

extern "C" void kernel_launch(void* const* d_in, const int* in_sizes, int n_in,
                              void* d_out, int out_size) {
    const float* X = (const float*)d_in[0];   // [4096, 12] fp32
    const float* W = (const float*)d_in[1];   // [8, 12]    fp32
    float* out = (float*)d_out;               // [4096, 10] fp32
    const int batch = in_sizes[0] / 12;
    vqc_kernel<<<batch, NT>>>(X, W, out);
}

// round 15
// speedup vs baseline: 1.0785x; 1.0785x over previous
#include <cuda_runtime.h>

#define DEPTH   8
#define NCLASS  10
#define NT      64
#define NREG    32    // float2 elements per thread; NT*NREG = 2048 = DIM/2

typedef unsigned long long u64;

// Swizzle v3: S(e) = e ^ ((e>>4)&14) ^ (e10<<3). Conflict-freedom verified
// by GF(2) rank analysis for ALL four patterns at their access widths:
//   store-B/load-B (u64, 16-lane phase): [t1, t2^r0, t3^r1, t0^t4^r2] rank4
//   gather        (u128,  8-lane phase): [t0+t1+t2, t1+t2, t0+t2]     rank3
//   store-A       (u128,  8-lane phase): [r1^t0, r2^t1, r3^t2]        rank3
// bit0 untouched -> u128 bases even, pairing fully compile-time.
__device__ __host__ constexpr int Sz3(int e) {
    return e ^ ((e >> 4) & 14) ^ (((e >> 10) & 1) << 3);
}
// CNOT-layer composite map in element space: old_e = Emap(new_e).
__device__ __host__ constexpr int Emap(int e) {
    return e ^ (e >> 1) ^ ((e >> 2) & 0x2AA);
}
__device__ __host__ constexpr int CBr(int r)  { return (r << 5) ^ ((r & 7) << 1); } // Sz3(r<<5)
__device__ __host__ constexpr int CGr(int r)  { return Emap(r); }  // = Sz3(Emap(r)), r<32
__device__ __host__ constexpr bool SWP(int r) { return ((r ^ (r >> 1)) & 1) != 0; }

#define PACK2(d,x,y)   asm("mov.b64 %0,{%1,%2};" : "=l"(d) : "f"(x),"f"(y))
#define UNPACK2(x,y,d) asm("mov.b64 {%0,%1},%2;" : "=f"(x),"=f"(y) : "l"(d))
#define MUL2(d,a,b)    asm("mul.rn.f32x2 %0,%1,%2;" : "=l"(d) : "l"(a),"l"(b))
#define FMA2(d,a,b,c)  asm("fma.rn.f32x2 %0,%1,%2,%3;" : "=l"(d) : "l"(a),"l"(b),"l"(c))

// Scaled-shear RY butterfly on 32 u64 regs along register-bit mask m.
// Cos factors hoisted out (global product applied to final probabilities).
__device__ __forceinline__ void shear32(u64* P, int m, u64 T2, u64 NT2) {
#pragma unroll
    for (int k = 0; k < NREG; k++)
        if (!(k & m)) {
            u64 n0, n1;
            FMA2(n0, NT2, P[k | m], P[k]);     // b0 = a0 - p*a1
            FMA2(n1, T2,  P[k],     P[k | m]); // b1 = a1 + p*a0
            P[k]     = n0;
            P[k | m] = n1;
        }
}

__global__ __launch_bounds__(NT, 8) void vqc_kernel(const float* __restrict__ X,
                                                    const float* __restrict__ W,
                                                    float* __restrict__ out) {
    __shared__ __align__(16) u64 smB[2048];           // SINGLE statevector buffer
    __shared__ u64 TT2[DEPTH * 12], NT2s[DEPTH * 12]; // packed tan / -tan
    __shared__ float t0s[DEPTH];                      // scalar tan, qubit 0
    __shared__ float t11s[DEPTH];                     // scalar tan, qubit 11
    __shared__ float cosv[DEPTH * 12];                // per-gate cos (parallel)
    __shared__ float enc0[12], enc1[12];
    __shared__ float red[2][NCLASS];

    const int t = threadIdx.x;

    // ---- coefficient tables (parallel across threads) ----
    for (int i = t; i < DEPTH * 12; i += NT) {
        float s_, c_;
        sincosf(0.5f * W[i], &s_, &c_);
        float tp = s_ / c_;                   // tan(phi/2)
        float nt = -tp;
        u64 a, b;
        PACK2(a, tp, tp);  PACK2(b, nt, nt);
        TT2[i] = a;  NT2s[i] = b;
        cosv[i] = c_;
        const int q = i % 12, k = i / 12;
        if (q == 0)  t0s[k]  = tp;
        if (q == 11) t11s[k] = tp;
    }
    if (t < 12) {
        float s_, c_;
        sincosf(0.5f * X[blockIdx.x * 12 + t], &s_, &c_);
        const float rr = 0.7071067811865476f;
        enc0[t] = (c_ - s_) * rr;
        enc1[t] = (c_ + s_) * rr;
    }
    __syncthreads();

    // ---- per-thread address bases (Sz3) ----
    // Tiling A: e = (t<<5)|r   (regs = e4..0 -> qubits 6..10)
    // Tiling B: e = (t0<<10)|(r<<5)|((t>>1)&31)  (regs = e9..5 -> qubits 1..5)
    const int bA = (t << 5) ^ ((t & 7) << 1) ^ (((t >> 5) & 1) << 3);   // even
    const int bB = ((t & 1) << 10) ^ ((t & 1) << 3) ^ ((t >> 1) & 31);
    int em = (t << 5) ^ (t << 4) ^ ((t << 3) & 0x2AA);  // Emap(t<<5)
    const int bG = Sz3(em);                             // even
    const int blkG = bG >> 1;
    const int blkA = bA >> 1;

    // ---- init: product state (H + encoding RY) in tiling B registers ----
    // thread bits: q0<-t0, q6<-t5, q7<-t4, q8<-t3, q9<-t2, q10<-t1
    float base = (t & 1)        ? enc1[0]  : enc0[0];
    base *= ((t >> 5) & 1)      ? enc1[6]  : enc0[6];
    base *= ((t >> 4) & 1)      ? enc1[7]  : enc0[7];
    base *= ((t >> 3) & 1)      ? enc1[8]  : enc0[8];
    base *= ((t >> 2) & 1)      ? enc1[9]  : enc0[9];
    base *= ((t >> 1) & 1)      ? enc1[10] : enc0[10];
    const float bx = base * enc0[11], by = base * enc1[11];

    u64 P[NREG];
#pragma unroll
    for (int r = 0; r < NREG; r++) {
        // reg bits: q1<-r4, q2<-r3, q3<-r2, q4<-r1, q5<-r0
        float rf = (r & 16) ? enc1[1] : enc0[1];
        rf *= (r & 8) ? enc1[2] : enc0[2];
        rf *= (r & 4) ? enc1[3] : enc0[3];
        rf *= (r & 2) ? enc1[4] : enc0[4];
        rf *= (r & 1) ? enc1[5] : enc0[5];
        float x = rf * bx, y = rf * by;
        PACK2(P[r], x, y);
    }

#pragma unroll 1
    for (int k = 0; k < DEPTH; k++) {
        const int kc = k * 12;

        // ---- trip 1: store B (u64) -> gather (u128) + q11 shear ----
#pragma unroll
        for (int r = 0; r < NREG; r++)
            smB[bB ^ CBr(r)] = P[r];
        __syncthreads();                       // store-B visible before gather

        const float t11 = t11s[k];
#pragma unroll
        for (int r = 0; r < NREG; r += 2) {
            // pair (r, r+1): Emap(r)^Emap(r+1)=1 -> one aligned 16B block.
            const int blk = blkG ^ (CGr(r) >> 1);
            ulonglong2 L = ((const ulonglong2*)smB)[blk];
            const bool hiFirst = (CGr(r) & 1) != 0;     // = (r>>1)&1
            u64 e0 = hiFirst ? L.y : L.x;               // element for P[r]
            u64 e1 = hiFirst ? L.x : L.y;               // element for P[r+1]
            {
                float x, y;
                UNPACK2(x, y, e0);
                float xx = SWP(r)     ? y : x;
                float yy = SWP(r)     ? x : y;
                float u = fmaf(-t11, yy, xx);
                float v = fmaf( t11, xx, yy);
                PACK2(P[r], u, v);
            }
            {
                float x, y;
                UNPACK2(x, y, e1);
                float xx = SWP(r + 1) ? y : x;
                float yy = SWP(r + 1) ? x : y;
                float u = fmaf(-t11, yy, xx);
                float v = fmaf( t11, xx, yy);
                PACK2(P[r + 1], u, v);
            }
        }
        __syncthreads();                       // gather reads done before store-A
        shear32(P, 16, TT2[kc + 6],  NT2s[kc + 6]);   // q6  <-> r4
        shear32(P, 8,  TT2[kc + 7],  NT2s[kc + 7]);   // q7
        shear32(P, 4,  TT2[kc + 8],  NT2s[kc + 8]);   // q8
        shear32(P, 2,  TT2[kc + 9],  NT2s[kc + 9]);   // q9
        shear32(P, 1,  TT2[kc + 10], NT2s[kc + 10]);  // q10

        // ---- trip 2: store A (u128) -> load B (u64) -> q1..q5 + shfl q0 ----
        // Sz3(r) = r for r<32, so store-A addr = bA ^ r; pairs along r0.
#pragma unroll
        for (int r = 0; r < NREG; r += 2) {
            ulonglong2 V;
            V.x = P[r];                        // addr bit0 = r0 -> even r = .x
            V.y = P[r + 1];
            ((ulonglong2*)smB)[blkA ^ (r >> 1)] = V;
        }
        __syncthreads();                       // store-A visible before load-B
#pragma unroll
        for (int r = 0; r < NREG; r++)
            P[r] = smB[bB ^ CBr(r)];

        shear32(P, 16, TT2[kc + 1], NT2s[kc + 1]);    // q1 <-> r4
        shear32(P, 8,  TT2[kc + 2], NT2s[kc + 2]);
        shear32(P, 4,  TT2[kc + 3], NT2s[kc + 3]);
        shear32(P, 2,  TT2[kc + 4], NT2s[kc + 4]);
        shear32(P, 1,  TT2[kc + 5], NT2s[kc + 5]);

        // qubit 0 on lane bit t0: shear via shfl (1 FMA2 per reg)
        {
            const float t0c = t0s[k];
            const float te = (t & 1) ? t0c : -t0c;
            u64 TE2;
            PACK2(TE2, te, te);
#pragma unroll
            for (int r = 0; r < NREG; r++) {
                u64 part = __shfl_xor_sync(0xffffffffu, P[r], 1);
                FMA2(P[r], TE2, part, P[r]);   // b = a ± p*partner
            }
        }
    }

    // ---- measurement from registers (tiling B) ----
    float T = 0.0f, A1 = 0.0f, A2 = 0.0f, A3 = 0.0f, A4 = 0.0f, A5 = 0.0f;
#pragma unroll
    for (int r = 0; r < NREG; r++) {
        float x, y;
        UNPACK2(x, y, P[r]);
        float p2 = fmaf(y, y, x * x);
        T += p2;
        if (!(r & 16)) A1 += p2;
        if (!(r & 8))  A2 += p2;
        if (!(r & 4))  A3 += p2;
        if (!(r & 2))  A4 += p2;
        if (!(r & 1))  A5 += p2;
    }
    // global cos-product correction (values computed in parallel earlier)
    float CT = 1.0f;
#pragma unroll
    for (int i = 0; i < DEPTH * 12; i++)
        CT *= cosv[i];
    const float CT2 = CT * CT;
    T *= CT2;  A1 *= CT2;  A2 *= CT2;  A3 *= CT2;  A4 *= CT2;  A5 *= CT2;

    float loc[NCLASS];
    loc[0] = (t & 1)        ? -T : T;
    loc[1] = 2.0f * A1 - T;
    loc[2] = 2.0f * A2 - T;
    loc[3] = 2.0f * A3 - T;
    loc[4] = 2.0f * A4 - T;
    loc[5] = 2.0f * A5 - T;
    loc[6] = ((t >> 5) & 1) ? -T : T;
    loc[7] = ((t >> 4) & 1) ? -T : T;
    loc[8] = ((t >> 3) & 1) ? -T : T;
    loc[9] = ((t >> 2) & 1) ? -T : T;

#pragma unroll
    for (int p = 0; p < NCLASS; p++) {
        float v = loc[p];
#pragma unroll
        for (int o = 16; o > 0; o >>= 1)
            v += __shfl_xor_sync(0xffffffffu, v, o);
        if ((t & 31) == 0) red[t >> 5][p] = v;
    }
    __syncthreads();
    if (t < NCLASS)
        out[blockIdx.x * NCLASS + t] = red[0][t] + red[1][t];
}

extern "C" void kernel_launch(void* const* d_in, const int* in_sizes, int n_in,
                              void* d_out, int out_size) {
    const float* X = (const float*)d_in[0];   // [4096, 12] fp32
    const float* W = (const float*)d_in[1];   // [8, 12]    fp32
    float* out = (float*)d_out;               // [4096, 10] fp32
    const int batch = in_sizes[0] / 12;
    vqc_kernel<<<batch, NT>>>(X, W, out);
}

// round 16
// speedup vs baseline: 1.1628x; 1.0782x over previous
#include <cuda_runtime.h>

#define DEPTH   8
#define NCLASS  10
#define NT      32
#define NREG    64    // float2 elements per thread; NT*NREG = 2048 = DIM/2

typedef unsigned long long u64;

// Address layout (GF(2)-linear bijection), bank-conflict-free u64 for all
// three patterns (rank-4 on half-warp low-4 address bits):
//   store/load-B dirs {L(e1..e4)} -> {2,4,8,1}
//   gather dirs {L(Emap(e6..e9))} -> {1,3,6,14}
//   store-A dirs {L(e6..e9)}      -> {1,2,4,8}
__device__ __host__ constexpr int Lmap(int e) {
    return e ^ ((e >> 4) & 1) ^ ((e >> 6) & 15);
}
// CNOT-layer composite map in element space: old_e = Emap(new_e);
// component swap when (e0 ^ e1) of the NEW element = 1.
__device__ __host__ constexpr int Emap(int e) {
    return e ^ (e >> 1) ^ ((e >> 2) & 0x2AA);
}
__device__ __host__ constexpr int CA(int r) { return r ^ ((r >> 4) & 1); }       // L(r), r<64
__device__ __host__ constexpr int CG(int r) { return Lmap(Emap(r)); }            // r<64
__device__ __host__ constexpr int CB(int r) {                                    // L(eBr(r))
    return ((((r >> 1) << 6) | (r & 1)) ^ ((r >> 1) & 15));
}
__device__ __host__ constexpr bool SWP(int r) { return ((r ^ (r >> 1)) & 1) != 0; }

#define PACK2(d,x,y)   asm("mov.b64 %0,{%1,%2};" : "=l"(d) : "f"(x),"f"(y))
#define UNPACK2(x,y,d) asm("mov.b64 {%0,%1},%2;" : "=f"(x),"=f"(y) : "l"(d))
#define FMA2(d,a,b,c)  asm("fma.rn.f32x2 %0,%1,%2,%3;" : "=l"(d) : "l"(a),"l"(b),"l"(c))

// Scaled-shear RY butterfly on 64 u64 regs along register-bit mask m.
// Cos factors hoisted out (global product applied to final probabilities).
__device__ __forceinline__ void shear64(u64* P, int m, u64 T2, u64 NT2) {
#pragma unroll
    for (int k = 0; k < NREG; k++)
        if (!(k & m)) {
            u64 n0, n1;
            FMA2(n0, NT2, P[k | m], P[k]);     // b0 = a0 - p*a1
            FMA2(n1, T2,  P[k],     P[k | m]); // b1 = a1 + p*a0
            P[k]     = n0;
            P[k | m] = n1;
        }
}

__global__ __launch_bounds__(NT, 12) void vqc_kernel(const float* __restrict__ X,
                                                     const float* __restrict__ W,
                                                     float* __restrict__ out) {
    __shared__ u64 smB[2048];                         // statevector buffer
    __shared__ u64 TT2[DEPTH * 12], NT2s[DEPTH * 12]; // packed tan / -tan
    __shared__ float t11s[DEPTH];                     // scalar tan, qubit 11
    __shared__ float cosv[DEPTH * 12];                // per-gate cos (parallel)
    __shared__ float enc0[12], enc1[12];

    const int t = threadIdx.x;

    // ---- coefficient tables (parallel across the warp) ----
    for (int i = t; i < DEPTH * 12; i += NT) {
        float s_, c_;
        sincosf(0.5f * W[i], &s_, &c_);
        float tp = s_ / c_;                   // tan(phi/2)
        float nt = -tp;
        u64 a, b;
        PACK2(a, tp, tp);  PACK2(b, nt, nt);
        TT2[i] = a;  NT2s[i] = b;
        cosv[i] = c_;
        if (i % 12 == 11) t11s[i / 12] = tp;
    }
    if (t < 12) {
        float s_, c_;
        sincosf(0.5f * X[blockIdx.x * 12 + t], &s_, &c_);
        const float rr = 0.7071067811865476f;
        enc0[t] = (c_ - s_) * rr;
        enc1[t] = (c_ + s_) * rr;
    }
    __syncwarp();

    // ---- per-thread address bases ----
    // Tiling A: e = (t<<6)|r   regs: r5..r0 = e5..e0 -> qubits q5..q10
    // Tiling B: e = ((r>>1)<<6)|(t<<1)|(r&1)
    //           regs: r5..r1 = e10..e6 -> q0..q4, r0 = e0 (= q10, no rot)
    //           thread: t4..t0 = e5..e1 -> q5..q9
    const int bA = (t << 6) ^ (t & 15);                 // Lmap(t<<6)
    const int bB = (t << 1) ^ ((t >> 3) & 1);           // Lmap(t<<1)
    int em = (t << 6);
    em = em ^ (em >> 1) ^ ((em >> 2) & 0x2AA);          // Emap(t<<6)
    const int bG = Lmap(em);

    // ---- init: product state (H + encoding RY) in tiling B registers ----
    float base = (t & 16) ? enc1[5] : enc0[5];          // q5 = t4
    base *= (t & 8)  ? enc1[6] : enc0[6];               // q6 = t3
    base *= (t & 4)  ? enc1[7] : enc0[7];               // q7 = t2
    base *= (t & 2)  ? enc1[8] : enc0[8];               // q8 = t1
    base *= (t & 1)  ? enc1[9] : enc0[9];               // q9 = t0
    const float bx = base * enc0[11], by = base * enc1[11];

    u64 P[NREG];
#pragma unroll
    for (int r = 0; r < NREG; r++) {
        // reg bits: q0<-r5, q1<-r4, q2<-r3, q3<-r2, q4<-r1, q10<-r0
        float rf = (r & 32) ? enc1[0]  : enc0[0];
        rf *= (r & 16) ? enc1[1]  : enc0[1];
        rf *= (r & 8)  ? enc1[2]  : enc0[2];
        rf *= (r & 4)  ? enc1[3]  : enc0[3];
        rf *= (r & 2)  ? enc1[4]  : enc0[4];
        rf *= (r & 1)  ? enc1[10] : enc0[10];
        float x = rf * bx, y = rf * by;
        PACK2(P[r], x, y);
    }

#pragma unroll 1
    for (int k = 0; k < DEPTH; k++) {
        const int kc = k * 12;

        // ---- trip 1: store B -> gather (CNOT perm) + q11 shear -> q5..q10
#pragma unroll
        for (int r = 0; r < NREG; r++)
            smB[bB ^ CB(r)] = P[r];
        __syncwarp();                          // store-B visible before gather

        const float t11 = t11s[k];
#pragma unroll
        for (int r = 0; r < NREG; r++) {
            float2 L = ((const float2*)smB)[bG ^ CG(r)];
            float x = SWP(r) ? L.y : L.x;      // compile-time component swap
            float y = SWP(r) ? L.x : L.y;
            float u = fmaf(-t11, y, x);        // SIMD qubit 11 shear
            float v = fmaf( t11, x, y);
            PACK2(P[r], u, v);
        }
        __syncwarp();                          // gather done before store-A
        shear64(P, 32, TT2[kc + 5],  NT2s[kc + 5]);   // q5  <-> r5
        shear64(P, 16, TT2[kc + 6],  NT2s[kc + 6]);   // q6
        shear64(P, 8,  TT2[kc + 7],  NT2s[kc + 7]);   // q7
        shear64(P, 4,  TT2[kc + 8],  NT2s[kc + 8]);   // q8
        shear64(P, 2,  TT2[kc + 9],  NT2s[kc + 9]);   // q9
        shear64(P, 1,  TT2[kc + 10], NT2s[kc + 10]);  // q10 <-> r0

        // ---- trip 2: store A -> load B (transpose) -> q0..q4 shears ----
#pragma unroll
        for (int r = 0; r < NREG; r++)
            smB[bA ^ CA(r)] = P[r];
        __syncwarp();                          // store-A visible before load-B
#pragma unroll
        for (int r = 0; r < NREG; r++)
            P[r] = smB[bB ^ CB(r)];

        shear64(P, 32, TT2[kc + 0], NT2s[kc + 0]);    // q0 <-> r5
        shear64(P, 16, TT2[kc + 1], NT2s[kc + 1]);    // q1
        shear64(P, 8,  TT2[kc + 2], NT2s[kc + 2]);    // q2
        shear64(P, 4,  TT2[kc + 3], NT2s[kc + 3]);    // q3
        shear64(P, 2,  TT2[kc + 4], NT2s[kc + 4]);    // q4 <-> r1
        __syncwarp();                          // load-B done before next store-B
    }

    // ---- measurement from registers (tiling B) ----
    float T = 0.0f, A0 = 0.0f, A1 = 0.0f, A2 = 0.0f, A3 = 0.0f, A4 = 0.0f;
#pragma unroll
    for (int r = 0; r < NREG; r++) {
        float x, y;
        UNPACK2(x, y, P[r]);
        float p2 = fmaf(y, y, x * x);
        T += p2;
        if (!(r & 32)) A0 += p2;
        if (!(r & 16)) A1 += p2;
        if (!(r & 8))  A2 += p2;
        if (!(r & 4))  A3 += p2;
        if (!(r & 2))  A4 += p2;
    }
    // global cos-product correction (values computed in parallel earlier)
    float CT = 1.0f;
#pragma unroll
    for (int i = 0; i < DEPTH * 12; i++)
        CT *= cosv[i];
    const float CT2 = CT * CT;
    T *= CT2;  A0 *= CT2;  A1 *= CT2;  A2 *= CT2;  A3 *= CT2;  A4 *= CT2;

    float loc[NCLASS];
    loc[0] = 2.0f * A0 - T;             // q0 = r5
    loc[1] = 2.0f * A1 - T;             // q1 = r4
    loc[2] = 2.0f * A2 - T;             // q2 = r3
    loc[3] = 2.0f * A3 - T;             // q3 = r2
    loc[4] = 2.0f * A4 - T;             // q4 = r1
    loc[5] = (t & 16) ? -T : T;         // q5 = t4
    loc[6] = (t & 8)  ? -T : T;         // q6 = t3
    loc[7] = (t & 4)  ? -T : T;         // q7 = t2
    loc[8] = (t & 2)  ? -T : T;         // q8 = t1
    loc[9] = (t & 1)  ? -T : T;         // q9 = t0

#pragma unroll
    for (int p = 0; p < NCLASS; p++) {
#pragma unroll
        for (int o = 16; o > 0; o >>= 1)
            loc[p] += __shfl_xor_sync(0xffffffffu, loc[p], o);
    }
    if (t < NCLASS) {
        float o = loc[0];
#pragma unroll
        for (int p = 1; p < NCLASS; p++)
            if (t == p) o = loc[p];
        out[blockIdx.x * NCLASS + t] = o;
    }
}

extern "C" void kernel_launch(void* const* d_in, const int* in_sizes, int n_in,
                              void* d_out, int out_size) {
    const float* X = (const float*)d_in[0];   // [4096, 12] fp32
    const float* W = (const float*)d_in[1];   // [8, 12]    fp32
    float* out = (float*)d_out;               // [4096, 10] fp32
    const int batch = in_sizes[0] / 12;
    vqc_kernel<<<batch, NT>>>(X, W, out);
}

// round 17
// speedup vs baseline: 1.2905x; 1.1098x over previous
#include <cuda_runtime.h>

#define DEPTH   8
#define NCLASS  10
#define NT      32
#define NREG    64    // float2 elements per thread; NT*NREG = 2048 = DIM/2

typedef unsigned long long u64;

// Layout v4: L(e) = e ^ ((e>>5)&14) ^ ((e>>4)&1).
// Rank-verified conflict-free at access width for all three patterns:
//   store/load-B (u64,16-lane):  [t2^r3, t1^r2, t0^r1, r0^t3]  rank 4
//   gather      (u128, 8-lane):  [t2, t1^t2, t0^t1]            rank 3
//   store-A     (u128, 8-lane):  [r3^t2, r2^t1, r1^t0]         rank 3
// bit0 = e0^e4 -> u128 pair bases aligned, half-selects compile-time.
__device__ __host__ constexpr int Lmap(int e) {
    return e ^ ((e >> 5) & 14) ^ ((e >> 4) & 1);
}
// CNOT-layer composite map in element space: old_e = Emap(new_e);
// component swap when (e0 ^ e1) of the NEW element = 1.
__device__ __host__ constexpr int Emap(int e) {
    return e ^ (e >> 1) ^ ((e >> 2) & 0x2AA);
}
__device__ __host__ constexpr int CAn(int r) { return Lmap(r); }          // r<64
__device__ __host__ constexpr int CGn(int r) { return Lmap(Emap(r)); }    // r<64
__device__ __host__ constexpr int CBn(int r) {
    return Lmap((((r >> 1) << 6) | (r & 1)));
}
__device__ __host__ constexpr bool SWP(int r) { return ((r ^ (r >> 1)) & 1) != 0; }

#define PACK2(d,x,y)   asm("mov.b64 %0,{%1,%2};" : "=l"(d) : "f"(x),"f"(y))
#define UNPACK2(x,y,d) asm("mov.b64 {%0,%1},%2;" : "=f"(x),"=f"(y) : "l"(d))
#define FMA2(d,a,b,c)  asm("fma.rn.f32x2 %0,%1,%2,%3;" : "=l"(d) : "l"(a),"l"(b),"l"(c))

// Scaled-shear RY butterfly on 64 u64 regs along register-bit mask m.
// -tan formed in-register (one XOR per call) — no second table.
__device__ __forceinline__ void shear64(u64* P, int m, u64 T2) {
    const u64 NT2 = T2 ^ 0x8000000080000000ULL;
#pragma unroll
    for (int k = 0; k < NREG; k++)
        if (!(k & m)) {
            u64 n0, n1;
            FMA2(n0, NT2, P[k | m], P[k]);     // b0 = a0 - p*a1
            FMA2(n1, T2,  P[k],     P[k | m]); // b1 = a1 + p*a0
            P[k]     = n0;
            P[k | m] = n1;
        }
}

__global__ __launch_bounds__(NT, 12) void vqc_kernel(const float* __restrict__ X,
                                                     const float* __restrict__ W,
                                                     float* __restrict__ out) {
    __shared__ __align__(16) u64 smB[2048];   // statevector buffer
    __shared__ u64 TT2[DEPTH * 12];           // packed tan(phi/2)
    __shared__ float t11s[DEPTH];             // scalar tan, qubit 11
    __shared__ float cosv[DEPTH * 12];        // per-gate cos (parallel)
    __shared__ float enc0[12], enc1[12];

    const int t = threadIdx.x;

    // ---- coefficient tables (parallel across the warp) ----
    for (int i = t; i < DEPTH * 12; i += NT) {
        float s_, c_;
        sincosf(0.5f * W[i], &s_, &c_);
        float tp = s_ / c_;                   // tan(phi/2)
        u64 a;
        PACK2(a, tp, tp);
        TT2[i] = a;
        cosv[i] = c_;
        if (i % 12 == 11) t11s[i / 12] = tp;
    }
    if (t < 12) {
        float s_, c_;
        sincosf(0.5f * X[blockIdx.x * 12 + t], &s_, &c_);
        const float rr = 0.7071067811865476f;
        enc0[t] = (c_ - s_) * rr;
        enc1[t] = (c_ + s_) * rr;
    }
    __syncwarp();

    // ---- per-thread address bases ----
    // Tiling A: e = (t<<6)|r   regs: r5..r0 = e5..e0 -> qubits q5..q10
    // Tiling B: e = ((r>>1)<<6)|(t<<1)|(r&1)
    //           regs: r5..r1 = e10..e6 -> q0..q4, r0 = e0
    //           thread: t4..t0 = e5..e1 -> q5..q9
    const int bA = Lmap(t << 6);               // even (bit0 = e0^e4 = 0)
    const int bB = (t << 1) ^ ((t >> 3) & 1);  // Lmap(t<<1)
    int em = (t << 6);
    em = em ^ (em >> 1) ^ ((em >> 2) & 0x2AA); // Emap(t<<6)
    const int bG = Lmap(em);                   // even
    const int blkA = bA >> 1;
    const int blkG = bG >> 1;

    // ---- init: product state (H + encoding RY) in tiling B registers ----
    float base = (t & 16) ? enc1[5] : enc0[5];          // q5 = t4
    base *= (t & 8)  ? enc1[6] : enc0[6];               // q6 = t3
    base *= (t & 4)  ? enc1[7] : enc0[7];               // q7 = t2
    base *= (t & 2)  ? enc1[8] : enc0[8];               // q8 = t1
    base *= (t & 1)  ? enc1[9] : enc0[9];               // q9 = t0
    const float bx = base * enc0[11], by = base * enc1[11];

    u64 P[NREG];
#pragma unroll
    for (int r = 0; r < NREG; r++) {
        // reg bits: q0<-r5, q1<-r4, q2<-r3, q3<-r2, q4<-r1, q10<-r0
        float rf = (r & 32) ? enc1[0]  : enc0[0];
        rf *= (r & 16) ? enc1[1]  : enc0[1];
        rf *= (r & 8)  ? enc1[2]  : enc0[2];
        rf *= (r & 4)  ? enc1[3]  : enc0[3];
        rf *= (r & 2)  ? enc1[4]  : enc0[4];
        rf *= (r & 1)  ? enc1[10] : enc0[10];
        float x = rf * bx, y = rf * by;
        PACK2(P[r], x, y);
    }

#pragma unroll 1
    for (int k = 0; k < DEPTH; k++) {
        const int kc = k * 12;

        // ---- trip 1: store B (u64) -> gather (u128) + q11 shear ----
        // store-B writes the same per-thread address set the previous
        // load-B read -> intra-thread WAR only, no sync needed before it.
#pragma unroll
        for (int r = 0; r < NREG; r++)
            smB[bB ^ CBn(r)] = P[r];
        __syncwarp();                          // store-B visible before gather

        const float t11 = t11s[k];
#pragma unroll
        for (int r = 0; r < NREG; r += 2) {
            // pair (r, r+1): Emap flips only e0 -> one aligned 16B block.
            ulonglong2 L = ((const ulonglong2*)smB)[blkG ^ (CGn(r) >> 1)];
            const bool hiFirst = (CGn(r) & 1) != 0;
            u64 e0 = hiFirst ? L.y : L.x;      // element for P[r]
            u64 e1 = hiFirst ? L.x : L.y;      // element for P[r+1]
            {
                float x, y;
                UNPACK2(x, y, e0);
                float xx = SWP(r)     ? y : x;
                float yy = SWP(r)     ? x : y;
                float u = fmaf(-t11, yy, xx);  // SIMD qubit 11 shear
                float v = fmaf( t11, xx, yy);
                PACK2(P[r], u, v);
            }
            {
                float x, y;
                UNPACK2(x, y, e1);
                float xx = SWP(r + 1) ? y : x;
                float yy = SWP(r + 1) ? x : y;
                float u = fmaf(-t11, yy, xx);
                float v = fmaf( t11, xx, yy);
                PACK2(P[r + 1], u, v);
            }
        }
        __syncwarp();                          // gather done before store-A
        shear64(P, 32, TT2[kc + 5]);           // q5  <-> r5
        shear64(P, 16, TT2[kc + 6]);           // q6
        shear64(P, 8,  TT2[kc + 7]);           // q7
        shear64(P, 4,  TT2[kc + 8]);           // q8
        shear64(P, 2,  TT2[kc + 9]);           // q9
        shear64(P, 1,  TT2[kc + 10]);          // q10 <-> r0

        // ---- trip 2: store A (u128) -> load B (u64) -> q0..q4 shears ----
#pragma unroll
        for (int r = 0; r < NREG; r += 2) {
            // CAn(r)&1 = r4 for even r: selects which element is the low u64.
            ulonglong2 V;
            if (CAn(r) & 1) { V.x = P[r + 1]; V.y = P[r];     }
            else            { V.x = P[r];     V.y = P[r + 1]; }
            ((ulonglong2*)smB)[blkA ^ (CAn(r) >> 1)] = V;
        }
        __syncwarp();                          // store-A visible before load-B
#pragma unroll
        for (int r = 0; r < NREG; r++)
            P[r] = smB[bB ^ CBn(r)];

        shear64(P, 32, TT2[kc + 0]);           // q0 <-> r5
        shear64(P, 16, TT2[kc + 1]);           // q1
        shear64(P, 8,  TT2[kc + 2]);           // q2
        shear64(P, 4,  TT2[kc + 3]);           // q3
        shear64(P, 2,  TT2[kc + 4]);           // q4 <-> r1
        // no sync: next store-B reuses this thread's own address set.
    }

    // ---- measurement from registers (tiling B) ----
    float T = 0.0f, A0 = 0.0f, A1 = 0.0f, A2 = 0.0f, A3 = 0.0f, A4 = 0.0f;
#pragma unroll
    for (int r = 0; r < NREG; r++) {
        float x, y;
        UNPACK2(x, y, P[r]);
        float p2 = fmaf(y, y, x * x);
        T += p2;
        if (!(r & 32)) A0 += p2;
        if (!(r & 16)) A1 += p2;
        if (!(r & 8))  A2 += p2;
        if (!(r & 4))  A3 += p2;
        if (!(r & 2))  A4 += p2;
    }
    // global cos-product correction (values computed in parallel earlier)
    float CT = 1.0f;
#pragma unroll
    for (int i = 0; i < DEPTH * 12; i++)
        CT *= cosv[i];
    const float CT2 = CT * CT;
    T *= CT2;  A0 *= CT2;  A1 *= CT2;  A2 *= CT2;  A3 *= CT2;  A4 *= CT2;

    float loc[NCLASS];
    loc[0] = 2.0f * A0 - T;             // q0 = r5
    loc[1] = 2.0f * A1 - T;             // q1 = r4
    loc[2] = 2.0f * A2 - T;             // q2 = r3
    loc[3] = 2.0f * A3 - T;             // q3 = r2
    loc[4] = 2.0f * A4 - T;             // q4 = r1
    loc[5] = (t & 16) ? -T : T;         // q5 = t4
    loc[6] = (t & 8)  ? -T : T;         // q6 = t3
    loc[7] = (t & 4)  ? -T : T;         // q7 = t2
    loc[8] = (t & 2)  ? -T : T;         // q8 = t1
    loc[9] = (t & 1)  ? -T : T;         // q9 = t0

#pragma unroll
    for (int p = 0; p < NCLASS; p++) {
#pragma unroll
        for (int o = 16; o > 0; o >>= 1)
            loc[p] += __shfl_xor_sync(0xffffffffu, loc[p], o);
    }
    if (t < NCLASS) {
        float o = loc[0];
#pragma unroll
        for (int p = 1; p < NCLASS; p++)
            if (t == p) o = loc[p];
        out[blockIdx.x * NCLASS + t] = o;
    }
}

extern "C" void kernel_launch(void* const* d_in, const int* in_sizes, int n_in,
                              void* d_out, int out_size) {
    const float* X = (const float*)d_in[0];   // [4096, 12] fp32
    const float* W = (const float*)d_in[1];   // [8, 12]    fp32
    float* out = (float*)d_out;               // [4096, 10] fp32
    const int batch = in_sizes[0] / 12;
    vqc_kernel<<<batch, NT>>>(X, W, out);
}